// round 10
// baseline (speedup 1.0000x reference)
#include <cuda_runtime.h>
#include <cuda_fp16.h>
#include <stdint.h>

#define IN_F    768
#define HID     64
#define MTILE   256
#define THREADS 256
#define NSTEP1  48           // 768/16 k-steps for layer 1 (= chunks)
#define NSTEP2  4            // 64/16 for layer 2
#define DEPTH   4            // per-warp cp.async ring depth
#define WCHUNK  2048         // per-warp chunk buffer: 32 rows x 64B
#define WSLICE  (DEPTH * WCHUNK)

// ---------------- device scratch (no allocations allowed) ----------------
__device__ float g_w1d[HID * IN_F];            // dense W1^T [n][k]
__device__ float g_w2d[HID * HID];             // dense W2^T [n][k]
__device__ uint4 g_w1f[NSTEP1 * 8 * 32];       // B-fragments: (main b0,b1, resid b0,b1)
__device__ uint4 g_w2f[NSTEP2 * 8 * 32];
__device__ float g_w3[HID];

static __device__ __forceinline__ void mma16816(float* d, const uint32_t* a,
                                                uint32_t b0, uint32_t b1) {
    asm volatile(
        "mma.sync.aligned.m16n8k16.row.col.f32.f16.f16.f32 "
        "{%0,%1,%2,%3}, {%4,%5,%6,%7}, {%8,%9}, {%0,%1,%2,%3};"
        : "+f"(d[0]), "+f"(d[1]), "+f"(d[2]), "+f"(d[3])
        : "r"(a[0]), "r"(a[1]), "r"(a[2]), "r"(a[3]), "r"(b0), "r"(b1));
}
static __device__ __forceinline__ uint32_t pkh(__half a, __half b) {
    __half2 h = __halves2half2(a, b);
    return *reinterpret_cast<uint32_t*>(&h);
}
static __device__ __forceinline__ uint32_t pk2(float2 v) {
    __half2 h = __floats2half2_rn(v.x, v.y);
    return *reinterpret_cast<uint32_t*>(&h);
}
static __device__ __forceinline__ void cp_async8(uint32_t daddr, const void* src, int srcsz) {
    asm volatile("cp.async.ca.shared.global [%0], [%1], 8, %2;"
                 :: "r"(daddr), "l"(src), "r"(srcsz) : "memory");
}
static __device__ __forceinline__ void cp_commit() {
    asm volatile("cp.async.commit_group;" ::: "memory");
}
template <int N>
static __device__ __forceinline__ void cp_wait() {
    asm volatile("cp.async.wait_group %0;" :: "n"(N) : "memory");
}

// ---------------- prep: zero -> scatter -> pack fragments (validated) ------
__global__ void zero_kernel() {
    const int t = blockIdx.x * blockDim.x + threadIdx.x;
    const int n = gridDim.x * blockDim.x;
    for (int i = t; i < HID * IN_F; i += n) g_w1d[i] = 0.f;
    for (int i = t; i < HID * HID;  i += n) g_w2d[i] = 0.f;
    for (int i = t; i < HID;        i += n) g_w3[i]  = 0.f;
}

__global__ void scatter_kernel(const int* __restrict__ idx1, const float* __restrict__ val1, int nnz1,
                               const int* __restrict__ idx2, const float* __restrict__ val2, int nnz2,
                               const int* __restrict__ idx3, const float* __restrict__ val3, int nnz3)
{
    const int t = blockIdx.x * blockDim.x + threadIdx.x;
    const int n = gridDim.x * blockDim.x;
    // idx layout [2,nnz]: rows then cols. dense is [n(col)][k(row)].
    for (int i = t; i < nnz1; i += n)
        atomicAdd(&g_w1d[idx1[nnz1 + i] * IN_F + idx1[i]], val1[i]);
    for (int i = t; i < nnz2; i += n)
        atomicAdd(&g_w2d[idx2[nnz2 + i] * HID + idx2[i]], val2[i]);
    for (int i = t; i < nnz3; i += n)
        atomicAdd(&g_w3[idx3[i]], val3[i]);
}

__global__ void pack_kernel() {
    const int tid = threadIdx.x;
    if (blockIdx.x < NSTEP1) {                 // one block per k-step of W1
        const int s    = blockIdx.x;
        const int nb   = tid >> 5;
        const int lane = tid & 31;
        const int k0 = s * 16 + (lane & 3) * 2;
        const int n  = nb * 8 + (lane >> 2);
        const float m0 = g_w1d[n * IN_F + k0];
        const float m1 = g_w1d[n * IN_F + k0 + 1];
        const float m2 = g_w1d[n * IN_F + k0 + 8];
        const float m3 = g_w1d[n * IN_F + k0 + 9];
        const __half h0 = __float2half_rn(m0), h1 = __float2half_rn(m1);
        const __half h2 = __float2half_rn(m2), h3 = __float2half_rn(m3);
        uint4 u;
        u.x = pkh(h0, h1);
        u.y = pkh(h2, h3);
        u.z = pkh(__float2half_rn(m0 - __half2float(h0)), __float2half_rn(m1 - __half2float(h1)));
        u.w = pkh(__float2half_rn(m2 - __half2float(h2)), __float2half_rn(m3 - __half2float(h3)));
        g_w1f[(s * 8 + nb) * 32 + lane] = u;
    } else {                                   // last block packs all of W2
        for (int j = tid; j < NSTEP2 * 8 * 32; j += THREADS) {
            const int s    = j >> 8;
            const int nb   = (j >> 5) & 7;
            const int lane = j & 31;
            const int k0 = s * 16 + (lane & 3) * 2;
            const int n  = nb * 8 + (lane >> 2);
            const float m0 = g_w2d[n * HID + k0];
            const float m1 = g_w2d[n * HID + k0 + 1];
            const float m2 = g_w2d[n * HID + k0 + 8];
            const float m3 = g_w2d[n * HID + k0 + 9];
            const __half h0 = __float2half_rn(m0), h1 = __float2half_rn(m1);
            const __half h2 = __float2half_rn(m2), h3 = __float2half_rn(m3);
            uint4 u;
            u.x = pkh(h0, h1);
            u.y = pkh(h2, h3);
            u.z = pkh(__float2half_rn(m0 - __half2float(h0)), __float2half_rn(m1 - __half2float(h1)));
            u.w = pkh(__float2half_rn(m2 - __half2float(h2)), __float2half_rn(m3 - __half2float(h3)));
            g_w2f[(s * 8 + nb) * 32 + lane] = u;
        }
    }
}

// ---------------------------------------------------------------------------
// Main kernel: each warp streams ONLY its own 32 rows via cp.async into a
// warp-private 4-deep ring -> per-warp wait_group + __syncwarp is the entire
// synchronization; ZERO __syncthreads. Store-side swizzle (u + 2*row)&7 makes
// the A-fragment ld.shared.v2.f32 2-phase (minimum). h1 stays in registers.
// 64KB smem/CTA -> 2 CTAs/SM; warps fully decoupled for latency hiding.
// ---------------------------------------------------------------------------
extern __shared__ __align__(16) unsigned char smem[];

__global__ __launch_bounds__(THREADS, 2)
void mma_kernel(const float* __restrict__ x,
                const float* __restrict__ b1,
                const float* __restrict__ b2,
                const float* __restrict__ b3,
                float* __restrict__ out, int batch)
{
    uint32_t sb;
    asm("{ .reg .u64 t; cvta.to.shared.u64 t, %1; cvt.u32.u64 %0, t; }" : "=r"(sb) : "l"(smem));
    const int tid  = threadIdx.x;
    const int w    = tid >> 5;
    const int lane = tid & 31;
    const int row0 = blockIdx.x * MTILE;
    const bool full = (row0 + MTILE) <= batch;

    const uint32_t wbase = sb + (uint32_t)w * WSLICE;

    // ---- per-warp cp.async of one chunk: lane covers rows lane>>3-aligned ----
    // chunk-row r (0..31): 0-15 -> stripe0 rows w*16+r ; 16-31 -> stripe1 rows 128+w*16+(r-16)
    // store unit swizzle: phys_u = (u + 2*r) & 7
    auto issue = [&](int c) {
        const uint32_t dbase = wbase + (uint32_t)(c & (DEPTH - 1)) * WCHUNK;
        #pragma unroll
        for (int j = 0; j < 8; ++j) {
            const int r = j * 4 + (lane >> 3);          // 0..31
            const int u = lane & 7;                     // 8B unit in 64B row piece
            const int grow = row0 + ((r < 16) ? (w * 16 + r) : (112 + w * 16 + r));
            const int ok = (full || grow < batch) ? 8 : 0;
            const float* src = x + (size_t)grow * IN_F + c * 16 + u * 2;
            cp_async8(dbase + (uint32_t)(r * 64 + (((u + 2 * r) & 7) * 8)), src, ok);
        }
        cp_commit();
    };

    float acc0[32], acc1[32];
    #pragma unroll
    for (int i = 0; i < 32; ++i) { acc0[i] = 0.f; acc1[i] = 0.f; }

    // ---- prologue: fill the ring ----
    issue(0); issue(1); issue(2); issue(3);

    // ---- layer-1 mainloop: NO block barriers ----
    #pragma unroll 1
    for (int c = 0; c < NSTEP1; ++c) {
        cp_wait<3>();                  // this warp's chunk c landed
        __syncwarp();

        const uint32_t xb = wbase + (uint32_t)(c & (DEPTH - 1)) * WCHUNK;
        uint32_t af[8];
        {
            const int rl = lane >> 2;          // 0..7
            const int u  = lane & 3;
            float2 v;
            #pragma unroll
            for (int st = 0; st < 2; ++st) {
                const int rA = st * 16 + rl;          // chunk-row of frag row
                const int rB = rA + 8;
                const uint32_t aA0 = xb + (uint32_t)(rA * 64 + (((u     + 2 * rA) & 7) * 8));
                const uint32_t aB0 = xb + (uint32_t)(rB * 64 + (((u     + 2 * rB) & 7) * 8));
                const uint32_t aA1 = xb + (uint32_t)(rA * 64 + (((u + 4 + 2 * rA) & 7) * 8));
                const uint32_t aB1 = xb + (uint32_t)(rB * 64 + (((u + 4 + 2 * rB) & 7) * 8));
                asm volatile("ld.shared.v2.f32 {%0,%1}, [%2];" : "=f"(v.x), "=f"(v.y) : "r"(aA0));
                af[st * 4 + 0] = pk2(v);
                asm volatile("ld.shared.v2.f32 {%0,%1}, [%2];" : "=f"(v.x), "=f"(v.y) : "r"(aB0));
                af[st * 4 + 1] = pk2(v);
                asm volatile("ld.shared.v2.f32 {%0,%1}, [%2];" : "=f"(v.x), "=f"(v.y) : "r"(aA1));
                af[st * 4 + 2] = pk2(v);
                asm volatile("ld.shared.v2.f32 {%0,%1}, [%2];" : "=f"(v.x), "=f"(v.y) : "r"(aB1));
                af[st * 4 + 3] = pk2(v);
            }
        }

        const uint4* wf = g_w1f + (size_t)c * 256 + lane;
        #pragma unroll
        for (int nb = 0; nb < 8; ++nb) {
            const uint4 f = __ldg(wf + nb * 32);
            mma16816(acc0 + nb * 4, af,     f.x, f.y);
            mma16816(acc0 + nb * 4, af,     f.z, f.w);
            mma16816(acc1 + nb * 4, af + 4, f.x, f.y);
            mma16816(acc1 + nb * 4, af + 4, f.z, f.w);
        }

        if (c + 4 < NSTEP1) issue(c + 4);      // refill slot just vacated
    }

    // ---- h1 = relu(acc + b1), packed into A-fragment registers ----
    uint32_t hlo0[8], hhi0[8], hlo1[8], hhi1[8];
    #pragma unroll
    for (int nb = 0; nb < 8; ++nb) {
        const int n = nb * 8 + (lane & 3) * 2;
        const float ba = __ldg(b1 + n), bb = __ldg(b1 + n + 1);
        hlo0[nb] = pkh(__float2half_rn(fmaxf(acc0[nb * 4 + 0] + ba, 0.f)),
                       __float2half_rn(fmaxf(acc0[nb * 4 + 1] + bb, 0.f)));
        hhi0[nb] = pkh(__float2half_rn(fmaxf(acc0[nb * 4 + 2] + ba, 0.f)),
                       __float2half_rn(fmaxf(acc0[nb * 4 + 3] + bb, 0.f)));
        hlo1[nb] = pkh(__float2half_rn(fmaxf(acc1[nb * 4 + 0] + ba, 0.f)),
                       __float2half_rn(fmaxf(acc1[nb * 4 + 1] + bb, 0.f)));
        hhi1[nb] = pkh(__float2half_rn(fmaxf(acc1[nb * 4 + 2] + ba, 0.f)),
                       __float2half_rn(fmaxf(acc1[nb * 4 + 3] + bb, 0.f)));
    }

    // ---- layer-2 GEMM (K=64), A straight from registers ----
    float ac20[32], ac21[32];
    #pragma unroll
    for (int i = 0; i < 32; ++i) { ac20[i] = 0.f; ac21[i] = 0.f; }
    #pragma unroll
    for (int s = 0; s < NSTEP2; ++s) {
        const uint32_t a0r[4] = { hlo0[2 * s], hhi0[2 * s], hlo0[2 * s + 1], hhi0[2 * s + 1] };
        const uint32_t a1r[4] = { hlo1[2 * s], hhi1[2 * s], hlo1[2 * s + 1], hhi1[2 * s + 1] };
        const uint4* wf = g_w2f + (size_t)s * 256 + lane;
        #pragma unroll
        for (int nb = 0; nb < 8; ++nb) {
            const uint4 f = __ldg(wf + nb * 32);
            mma16816(ac20 + nb * 4, a0r, f.x, f.y);
            mma16816(ac20 + nb * 4, a0r, f.z, f.w);
            mma16816(ac21 + nb * 4, a1r, f.x, f.y);
            mma16816(ac21 + nb * 4, a1r, f.z, f.w);
        }
    }

    // ---- epilogue: out = relu(ac2 + b2) . w3 + b3 ----
    {
        const float b3v = __ldg(b3);
        #pragma unroll
        for (int st = 0; st < 2; ++st) {
            const float* ac = st ? ac21 : ac20;
            float pA = 0.f, pB = 0.f;
            #pragma unroll
            for (int nb = 0; nb < 8; ++nb) {
                const int n = nb * 8 + (lane & 3) * 2;
                const float ba = __ldg(b2 + n), bb = __ldg(b2 + n + 1);
                const float wa = g_w3[n],       wb = g_w3[n + 1];
                pA += fmaxf(ac[nb * 4 + 0] + ba, 0.f) * wa
                    + fmaxf(ac[nb * 4 + 1] + bb, 0.f) * wb;
                pB += fmaxf(ac[nb * 4 + 2] + ba, 0.f) * wa
                    + fmaxf(ac[nb * 4 + 3] + bb, 0.f) * wb;
            }
            pA += __shfl_xor_sync(0xffffffffu, pA, 1);
            pA += __shfl_xor_sync(0xffffffffu, pA, 2);
            pB += __shfl_xor_sync(0xffffffffu, pB, 1);
            pB += __shfl_xor_sync(0xffffffffu, pB, 2);
            if ((lane & 3) == 0) {
                const int rA = row0 + st * 128 + w * 16 + (lane >> 2);
                if (rA < batch)     out[rA]     = pA + b3v;
                if (rA + 8 < batch) out[rA + 8] = pB + b3v;
            }
        }
    }
}

// ---------------------------------------------------------------------------
extern "C" void kernel_launch(void* const* d_in, const int* in_sizes, int n_in,
                              void* d_out, int out_size)
{
    const float* x    = (const float*)d_in[0];
    const int*   idx1 = (const int*)  d_in[1];
    const float* val1 = (const float*)d_in[2];
    const float* b1   = (const float*)d_in[3];
    const int*   idx2 = (const int*)  d_in[4];
    const float* val2 = (const float*)d_in[5];
    const float* b2   = (const float*)d_in[6];
    const int*   idx3 = (const int*)  d_in[7];
    const float* val3 = (const float*)d_in[8];
    const float* b3   = (const float*)d_in[9];

    const int nnz1  = in_sizes[1] / 2;
    const int nnz2  = in_sizes[4] / 2;
    const int nnz3  = in_sizes[7] / 2;
    const int batch = in_sizes[0] / IN_F;

    const int smem_bytes = 8 * WSLICE;    // 8 warps * 8KB = 65536
    cudaFuncSetAttribute(mma_kernel, cudaFuncAttributeMaxDynamicSharedMemorySize, smem_bytes);

    zero_kernel<<<64, 256>>>();
    scatter_kernel<<<32, 256>>>(idx1, val1, nnz1, idx2, val2, nnz2, idx3, val3, nnz3);
    pack_kernel<<<NSTEP1 + 1, THREADS>>>();

    const int blocks = (batch + MTILE - 1) / MTILE;
    mma_kernel<<<blocks, THREADS, smem_bytes>>>(x, b1, b2, b3, (float*)d_out, batch);
}

// round 11
// speedup vs baseline: 1.2636x; 1.2636x over previous
#include <cuda_runtime.h>
#include <cuda_fp16.h>
#include <stdint.h>

#define IN_F    768
#define HID     64
#define MTILE   256
#define THREADS 256
#define NSTEP1  48           // 768/16 k-steps for layer 1 (= chunks)
#define NSTEP2  4            // 64/16 for layer 2
#define DEPTH   4            // cp.async ring depth
#define CHUNK_B 16384        // 256 rows x 16 K x 4B

// ---------------- device scratch (no allocations allowed) ----------------
__device__ float g_w1d[HID * IN_F];            // dense W1^T [n][k]
__device__ float g_w2d[HID * HID];             // dense W2^T [n][k]
__device__ uint2 g_w1m[NSTEP1 * 8 * 32];       // W1 B-fragments, main only (b0,b1)
__device__ uint4 g_w2f[NSTEP2 * 8 * 32];       // W2 B-fragments main+residual
__device__ float g_w3[HID];

static __device__ __forceinline__ void mma16816(float* d, const uint32_t* a,
                                                uint32_t b0, uint32_t b1) {
    asm volatile(
        "mma.sync.aligned.m16n8k16.row.col.f32.f16.f16.f32 "
        "{%0,%1,%2,%3}, {%4,%5,%6,%7}, {%8,%9}, {%0,%1,%2,%3};"
        : "+f"(d[0]), "+f"(d[1]), "+f"(d[2]), "+f"(d[3])
        : "r"(a[0]), "r"(a[1]), "r"(a[2]), "r"(a[3]), "r"(b0), "r"(b1));
}
static __device__ __forceinline__ uint32_t pkh(__half a, __half b) {
    __half2 h = __halves2half2(a, b);
    return *reinterpret_cast<uint32_t*>(&h);
}
static __device__ __forceinline__ uint32_t pk2(float2 v) {
    __half2 h = __floats2half2_rn(v.x, v.y);
    return *reinterpret_cast<uint32_t*>(&h);
}
static __device__ __forceinline__ void cp_async8(uint32_t daddr, const void* src, int srcsz) {
    asm volatile("cp.async.ca.shared.global [%0], [%1], 8, %2;"
                 :: "r"(daddr), "l"(src), "r"(srcsz) : "memory");
}
static __device__ __forceinline__ void cp_commit() {
    asm volatile("cp.async.commit_group;" ::: "memory");
}
template <int N>
static __device__ __forceinline__ void cp_wait() {
    asm volatile("cp.async.wait_group %0;" :: "n"(N) : "memory");
}

// ---------------- prep: zero -> scatter -> pack fragments ----------------
__global__ void zero_kernel() {
    const int t = blockIdx.x * blockDim.x + threadIdx.x;
    const int n = gridDim.x * blockDim.x;
    for (int i = t; i < HID * IN_F; i += n) g_w1d[i] = 0.f;
    for (int i = t; i < HID * HID;  i += n) g_w2d[i] = 0.f;
    for (int i = t; i < HID;        i += n) g_w3[i]  = 0.f;
}

__global__ void scatter_kernel(const int* __restrict__ idx1, const float* __restrict__ val1, int nnz1,
                               const int* __restrict__ idx2, const float* __restrict__ val2, int nnz2,
                               const int* __restrict__ idx3, const float* __restrict__ val3, int nnz3)
{
    const int t = blockIdx.x * blockDim.x + threadIdx.x;
    const int n = gridDim.x * blockDim.x;
    // idx layout [2,nnz]: rows then cols. dense is [n(col)][k(row)].
    for (int i = t; i < nnz1; i += n)
        atomicAdd(&g_w1d[idx1[nnz1 + i] * IN_F + idx1[i]], val1[i]);
    for (int i = t; i < nnz2; i += n)
        atomicAdd(&g_w2d[idx2[nnz2 + i] * HID + idx2[i]], val2[i]);
    for (int i = t; i < nnz3; i += n)
        atomicAdd(&g_w3[idx3[i]], val3[i]);
}

__global__ void pack_kernel() {
    const int tid = threadIdx.x;
    if (blockIdx.x < NSTEP1) {                 // one block per k-step of W1 (main only)
        const int s    = blockIdx.x;
        const int nb   = tid >> 5;
        const int lane = tid & 31;
        const int k0 = s * 16 + (lane & 3) * 2;
        const int n  = nb * 8 + (lane >> 2);
        const float m0 = g_w1d[n * IN_F + k0];
        const float m1 = g_w1d[n * IN_F + k0 + 1];
        const float m2 = g_w1d[n * IN_F + k0 + 8];
        const float m3 = g_w1d[n * IN_F + k0 + 9];
        uint2 u;
        u.x = pkh(__float2half_rn(m0), __float2half_rn(m1));
        u.y = pkh(__float2half_rn(m2), __float2half_rn(m3));
        g_w1m[(s * 8 + nb) * 32 + lane] = u;
    } else {                                   // last block packs all of W2 (main+resid)
        for (int j = tid; j < NSTEP2 * 8 * 32; j += THREADS) {
            const int s    = j >> 8;
            const int nb   = (j >> 5) & 7;
            const int lane = j & 31;
            const int k0 = s * 16 + (lane & 3) * 2;
            const int n  = nb * 8 + (lane >> 2);
            const float m0 = g_w2d[n * HID + k0];
            const float m1 = g_w2d[n * HID + k0 + 1];
            const float m2 = g_w2d[n * HID + k0 + 8];
            const float m3 = g_w2d[n * HID + k0 + 9];
            const __half h0 = __float2half_rn(m0), h1 = __float2half_rn(m1);
            const __half h2 = __float2half_rn(m2), h3 = __float2half_rn(m3);
            uint4 u;
            u.x = pkh(h0, h1);
            u.y = pkh(h2, h3);
            u.z = pkh(__float2half_rn(m0 - __half2float(h0)), __float2half_rn(m1 - __half2float(h1)));
            u.w = pkh(__float2half_rn(m2 - __half2float(h2)), __float2half_rn(m3 - __half2float(h3)));
            g_w2f[(s * 8 + nb) * 32 + lane] = u;
        }
    }
}

// ---------------------------------------------------------------------------
// Main kernel (R9 structure = best measured): x streamed fp32 via cp.async
// into a 4-deep block ring; A-fragments via LDS.64 + F2FP pack. Layer-1 uses
// MAIN fp16 weights only (16 MMAs + 16 B-wavefronts per k-step, one MMA per
// acc chain). Layer 2 keeps the fp16-residual pass (nearly free). h1 stays in
// registers. 64KB smem -> 2 CTAs/SM.
// ---------------------------------------------------------------------------
extern __shared__ __align__(16) unsigned char smem[];

__global__ __launch_bounds__(THREADS, 2)
void mma_kernel(const float* __restrict__ x,
                const float* __restrict__ b1,
                const float* __restrict__ b2,
                const float* __restrict__ b3,
                float* __restrict__ out, int batch)
{
    uint32_t sb;
    asm("{ .reg .u64 t; cvta.to.shared.u64 t, %1; cvt.u32.u64 %0, t; }" : "=r"(sb) : "l"(smem));
    const int tid  = threadIdx.x;
    const int w    = tid >> 5;
    const int lane = tid & 31;
    const int row0 = blockIdx.x * MTILE;
    const bool full = (row0 + MTILE) <= batch;

    // ---- cp.async issue of one 16-K chunk (8 copies/thread, coalesced) ----
    const int crow = tid >> 3;        // 0..31 (row within a 32-row pass)
    const int cu   = tid & 7;         // 8B unit within the 16-float row piece
    auto issue = [&](int c) {
        const uint32_t dbase = sb + (uint32_t)(c & (DEPTH - 1)) * CHUNK_B;
        #pragma unroll
        for (int j = 0; j < 8; ++j) {
            const int row = j * 32 + crow;
            const int ok = (full || (row0 + row) < batch) ? 8 : 0;
            const float* src = x + (size_t)(row0 + row) * IN_F + c * 16 + cu * 2;
            cp_async8(dbase + (uint32_t)(row * 64 + cu * 8), src, ok);
        }
        cp_commit();
    };

    // A-fragment LDS geometry (verified R8/R9 ordering)
    const uint32_t a0 = (uint32_t)((w * 16 + (lane >> 2)) * 64 + (lane & 3) * 8);

    float acc0[32], acc1[32];
    #pragma unroll
    for (int i = 0; i < 32; ++i) { acc0[i] = 0.f; acc1[i] = 0.f; }

    // ---- prologue: 3 chunks in flight ----
    issue(0); issue(1); issue(2);

    // ---- layer-1 mainloop over 48 chunks (= k-steps) ----
    #pragma unroll 1
    for (int c = 0; c < NSTEP1; ++c) {
        cp_wait<2>();                 // chunk c complete (for this thread)
        __syncthreads();              // all threads' copies for chunk c visible

        const uint32_t xb = sb + (uint32_t)(c & (DEPTH - 1)) * CHUNK_B;
        uint32_t af[8];
        {
            float2 v;
            asm volatile("ld.shared.v2.f32 {%0,%1}, [%2];" : "=f"(v.x), "=f"(v.y) : "r"(xb + a0));
            af[0] = pk2(v);
            asm volatile("ld.shared.v2.f32 {%0,%1}, [%2];" : "=f"(v.x), "=f"(v.y) : "r"(xb + a0 + 512));
            af[1] = pk2(v);
            asm volatile("ld.shared.v2.f32 {%0,%1}, [%2];" : "=f"(v.x), "=f"(v.y) : "r"(xb + a0 + 32));
            af[2] = pk2(v);
            asm volatile("ld.shared.v2.f32 {%0,%1}, [%2];" : "=f"(v.x), "=f"(v.y) : "r"(xb + a0 + 544));
            af[3] = pk2(v);
            asm volatile("ld.shared.v2.f32 {%0,%1}, [%2];" : "=f"(v.x), "=f"(v.y) : "r"(xb + a0 + 8192));
            af[4] = pk2(v);
            asm volatile("ld.shared.v2.f32 {%0,%1}, [%2];" : "=f"(v.x), "=f"(v.y) : "r"(xb + a0 + 8704));
            af[5] = pk2(v);
            asm volatile("ld.shared.v2.f32 {%0,%1}, [%2];" : "=f"(v.x), "=f"(v.y) : "r"(xb + a0 + 8224));
            af[6] = pk2(v);
            asm volatile("ld.shared.v2.f32 {%0,%1}, [%2];" : "=f"(v.x), "=f"(v.y) : "r"(xb + a0 + 8736));
            af[7] = pk2(v);
        }

        const uint2* wf = g_w1m + (size_t)c * 256 + lane;
        #pragma unroll
        for (int nb = 0; nb < 8; ++nb) {
            const uint2 f = __ldg(wf + nb * 32);
            mma16816(acc0 + nb * 4, af,     f.x, f.y);
            mma16816(acc1 + nb * 4, af + 4, f.x, f.y);
        }

        __syncthreads();              // all warps done reading buf c before refill
        if (c + 3 < NSTEP1) issue(c + 3);
    }

    // ---- h1 = relu(acc + b1), packed into A-fragment registers ----
    uint32_t hlo0[8], hhi0[8], hlo1[8], hhi1[8];
    #pragma unroll
    for (int nb = 0; nb < 8; ++nb) {
        const int n = nb * 8 + (lane & 3) * 2;
        const float ba = __ldg(b1 + n), bb = __ldg(b1 + n + 1);
        hlo0[nb] = pkh(__float2half_rn(fmaxf(acc0[nb * 4 + 0] + ba, 0.f)),
                       __float2half_rn(fmaxf(acc0[nb * 4 + 1] + bb, 0.f)));
        hhi0[nb] = pkh(__float2half_rn(fmaxf(acc0[nb * 4 + 2] + ba, 0.f)),
                       __float2half_rn(fmaxf(acc0[nb * 4 + 3] + bb, 0.f)));
        hlo1[nb] = pkh(__float2half_rn(fmaxf(acc1[nb * 4 + 0] + ba, 0.f)),
                       __float2half_rn(fmaxf(acc1[nb * 4 + 1] + bb, 0.f)));
        hhi1[nb] = pkh(__float2half_rn(fmaxf(acc1[nb * 4 + 2] + ba, 0.f)),
                       __float2half_rn(fmaxf(acc1[nb * 4 + 3] + bb, 0.f)));
    }

    // ---- layer-2 GEMM (K=64), A from registers, main + residual B ----
    float ac20[32], ac21[32];
    #pragma unroll
    for (int i = 0; i < 32; ++i) { ac20[i] = 0.f; ac21[i] = 0.f; }
    #pragma unroll
    for (int s = 0; s < NSTEP2; ++s) {
        const uint32_t a0r[4] = { hlo0[2 * s], hhi0[2 * s], hlo0[2 * s + 1], hhi0[2 * s + 1] };
        const uint32_t a1r[4] = { hlo1[2 * s], hhi1[2 * s], hlo1[2 * s + 1], hhi1[2 * s + 1] };
        const uint4* wf = g_w2f + (size_t)s * 256 + lane;
        #pragma unroll
        for (int nb = 0; nb < 8; ++nb) {
            const uint4 f = __ldg(wf + nb * 32);
            mma16816(ac20 + nb * 4, a0r, f.x, f.y);
            mma16816(ac20 + nb * 4, a0r, f.z, f.w);
            mma16816(ac21 + nb * 4, a1r, f.x, f.y);
            mma16816(ac21 + nb * 4, a1r, f.z, f.w);
        }
    }

    // ---- epilogue: out = relu(ac2 + b2) . w3 + b3 ----
    {
        const float b3v = __ldg(b3);
        #pragma unroll
        for (int st = 0; st < 2; ++st) {
            const float* ac = st ? ac21 : ac20;
            float pA = 0.f, pB = 0.f;
            #pragma unroll
            for (int nb = 0; nb < 8; ++nb) {
                const int n = nb * 8 + (lane & 3) * 2;
                const float ba = __ldg(b2 + n), bb = __ldg(b2 + n + 1);
                const float wa = g_w3[n],       wb = g_w3[n + 1];
                pA += fmaxf(ac[nb * 4 + 0] + ba, 0.f) * wa
                    + fmaxf(ac[nb * 4 + 1] + bb, 0.f) * wb;
                pB += fmaxf(ac[nb * 4 + 2] + ba, 0.f) * wa
                    + fmaxf(ac[nb * 4 + 3] + bb, 0.f) * wb;
            }
            pA += __shfl_xor_sync(0xffffffffu, pA, 1);
            pA += __shfl_xor_sync(0xffffffffu, pA, 2);
            pB += __shfl_xor_sync(0xffffffffu, pB, 1);
            pB += __shfl_xor_sync(0xffffffffu, pB, 2);
            if ((lane & 3) == 0) {
                const int rA = row0 + st * 128 + w * 16 + (lane >> 2);
                if (rA < batch)     out[rA]     = pA + b3v;
                if (rA + 8 < batch) out[rA + 8] = pB + b3v;
            }
        }
    }
}

// ---------------------------------------------------------------------------
extern "C" void kernel_launch(void* const* d_in, const int* in_sizes, int n_in,
                              void* d_out, int out_size)
{
    const float* x    = (const float*)d_in[0];
    const int*   idx1 = (const int*)  d_in[1];
    const float* val1 = (const float*)d_in[2];
    const float* b1   = (const float*)d_in[3];
    const int*   idx2 = (const int*)  d_in[4];
    const float* val2 = (const float*)d_in[5];
    const float* b2   = (const float*)d_in[6];
    const int*   idx3 = (const int*)  d_in[7];
    const float* val3 = (const float*)d_in[8];
    const float* b3   = (const float*)d_in[9];

    const int nnz1  = in_sizes[1] / 2;
    const int nnz2  = in_sizes[4] / 2;
    const int nnz3  = in_sizes[7] / 2;
    const int batch = in_sizes[0] / IN_F;

    const int smem_bytes = DEPTH * CHUNK_B;   // 65536
    cudaFuncSetAttribute(mma_kernel, cudaFuncAttributeMaxDynamicSharedMemorySize, smem_bytes);

    zero_kernel<<<64, 256>>>();
    scatter_kernel<<<32, 256>>>(idx1, val1, nnz1, idx2, val2, nnz2, idx3, val3, nnz3);
    pack_kernel<<<NSTEP1 + 1, THREADS>>>();

    const int blocks = (batch + MTILE - 1) / MTILE;
    mma_kernel<<<blocks, THREADS, smem_bytes>>>(x, b1, b2, b3, (float*)d_out, batch);
}

// round 12
// speedup vs baseline: 1.5726x; 1.2445x over previous
#include <cuda_runtime.h>
#include <cuda_fp16.h>
#include <stdint.h>

#define IN_F    768
#define HID     64
#define MTILE   256
#define THREADS 256
#define NSTEP1  48           // 768/16 k-steps for layer 1 (= chunks)
#define NSTEP2  4            // 64/16 for layer 2
#define DEPTH   4            // cp.async ring depth
#define CHUNK_B 16384        // 256 rows x 16 K x 4B

// ---------------- device scratch (no allocations allowed) ----------------
__device__ float g_w1d[HID * IN_F];            // dense W1^T [n][k]
__device__ float g_w2d[HID * HID];             // dense W2^T [n][k]
__device__ uint2 g_w1m[NSTEP1 * 8 * 32];       // W1 B-fragments, main only (b0,b1)
__device__ uint4 g_w2f[NSTEP2 * 8 * 32];       // W2 B-fragments main+residual
__device__ float g_w3[HID];

static __device__ __forceinline__ void mma16816(float* d, const uint32_t* a,
                                                uint32_t b0, uint32_t b1) {
    asm volatile(
        "mma.sync.aligned.m16n8k16.row.col.f32.f16.f16.f32 "
        "{%0,%1,%2,%3}, {%4,%5,%6,%7}, {%8,%9}, {%0,%1,%2,%3};"
        : "+f"(d[0]), "+f"(d[1]), "+f"(d[2]), "+f"(d[3])
        : "r"(a[0]), "r"(a[1]), "r"(a[2]), "r"(a[3]), "r"(b0), "r"(b1));
}
static __device__ __forceinline__ uint32_t pkh(__half a, __half b) {
    __half2 h = __halves2half2(a, b);
    return *reinterpret_cast<uint32_t*>(&h);
}
static __device__ __forceinline__ uint32_t pk2(float2 v) {
    __half2 h = __floats2half2_rn(v.x, v.y);
    return *reinterpret_cast<uint32_t*>(&h);
}
static __device__ __forceinline__ void cp_async16(uint32_t daddr, const void* src, int srcsz) {
    asm volatile("cp.async.cg.shared.global [%0], [%1], 16, %2;"
                 :: "r"(daddr), "l"(src), "r"(srcsz) : "memory");
}
static __device__ __forceinline__ void cp_commit() {
    asm volatile("cp.async.commit_group;" ::: "memory");
}
template <int N>
static __device__ __forceinline__ void cp_wait() {
    asm volatile("cp.async.wait_group %0;" :: "n"(N) : "memory");
}

// ---------------- prep: zero -> scatter -> pack fragments ----------------
__global__ void zero_kernel() {
    const int t = blockIdx.x * blockDim.x + threadIdx.x;
    const int n = gridDim.x * blockDim.x;
    for (int i = t; i < HID * IN_F; i += n) g_w1d[i] = 0.f;
    for (int i = t; i < HID * HID;  i += n) g_w2d[i] = 0.f;
    for (int i = t; i < HID;        i += n) g_w3[i]  = 0.f;
}

__global__ void scatter_kernel(const int* __restrict__ idx1, const float* __restrict__ val1, int nnz1,
                               const int* __restrict__ idx2, const float* __restrict__ val2, int nnz2,
                               const int* __restrict__ idx3, const float* __restrict__ val3, int nnz3)
{
    const int t = blockIdx.x * blockDim.x + threadIdx.x;
    const int n = gridDim.x * blockDim.x;
    // idx layout [2,nnz]: rows then cols. dense is [n(col)][k(row)].
    for (int i = t; i < nnz1; i += n)
        atomicAdd(&g_w1d[idx1[nnz1 + i] * IN_F + idx1[i]], val1[i]);
    for (int i = t; i < nnz2; i += n)
        atomicAdd(&g_w2d[idx2[nnz2 + i] * HID + idx2[i]], val2[i]);
    for (int i = t; i < nnz3; i += n)
        atomicAdd(&g_w3[idx3[i]], val3[i]);
}

__global__ void pack_kernel() {
    const int tid = threadIdx.x;
    if (blockIdx.x < NSTEP1) {                 // one block per k-step of W1 (main only)
        const int s    = blockIdx.x;
        const int nb   = tid >> 5;
        const int lane = tid & 31;
        const int k0 = s * 16 + (lane & 3) * 2;
        const int n  = nb * 8 + (lane >> 2);
        const float m0 = g_w1d[n * IN_F + k0];
        const float m1 = g_w1d[n * IN_F + k0 + 1];
        const float m2 = g_w1d[n * IN_F + k0 + 8];
        const float m3 = g_w1d[n * IN_F + k0 + 9];
        uint2 u;
        u.x = pkh(__float2half_rn(m0), __float2half_rn(m1));
        u.y = pkh(__float2half_rn(m2), __float2half_rn(m3));
        g_w1m[(s * 8 + nb) * 32 + lane] = u;
    } else {                                   // last block packs all of W2 (main+resid)
        for (int j = tid; j < NSTEP2 * 8 * 32; j += THREADS) {
            const int s    = j >> 8;
            const int nb   = (j >> 5) & 7;
            const int lane = j & 31;
            const int k0 = s * 16 + (lane & 3) * 2;
            const int n  = nb * 8 + (lane >> 2);
            const float m0 = g_w2d[n * HID + k0];
            const float m1 = g_w2d[n * HID + k0 + 1];
            const float m2 = g_w2d[n * HID + k0 + 8];
            const float m3 = g_w2d[n * HID + k0 + 9];
            const __half h0 = __float2half_rn(m0), h1 = __float2half_rn(m1);
            const __half h2 = __float2half_rn(m2), h3 = __float2half_rn(m3);
            uint4 u;
            u.x = pkh(h0, h1);
            u.y = pkh(h2, h3);
            u.z = pkh(__float2half_rn(m0 - __half2float(h0)), __float2half_rn(m1 - __half2float(h1)));
            u.w = pkh(__float2half_rn(m2 - __half2float(h2)), __float2half_rn(m3 - __half2float(h3)));
            g_w2f[(s * 8 + nb) * 32 + lane] = u;
        }
    }
}

// ---------------------------------------------------------------------------
// Main kernel (R11 structure, R12 deltas): 16B cp.async (half the LDGSTS
// instruction cost) and ONE __syncthreads per chunk (issue moved right after
// the leading barrier; WAR-safe since slot (c+3)&3 == (c-1)&3 and the barrier
// proves all warps finished reading chunk c-1). Layer-1 main-fp16 weights
// only; layer-2 keeps the residual pass; h1 register-resident.
// ---------------------------------------------------------------------------
extern __shared__ __align__(16) unsigned char smem[];

__global__ __launch_bounds__(THREADS, 2)
void mma_kernel(const float* __restrict__ x,
                const float* __restrict__ b1,
                const float* __restrict__ b2,
                const float* __restrict__ b3,
                float* __restrict__ out, int batch)
{
    uint32_t sb;
    asm("{ .reg .u64 t; cvta.to.shared.u64 t, %1; cvt.u32.u64 %0, t; }" : "=r"(sb) : "l"(smem));
    const int tid  = threadIdx.x;
    const int w    = tid >> 5;
    const int lane = tid & 31;
    const int row0 = blockIdx.x * MTILE;
    const bool full = (row0 + MTILE) <= batch;

    // ---- cp.async issue of one 16-K chunk: 16B copies, 4 per thread ----
    const int crow = tid >> 2;        // 0..63 (row within a 64-row pass)
    const int cu   = tid & 3;         // 16B unit within the 64B row piece
    auto issue = [&](int c) {
        const uint32_t dbase = sb + (uint32_t)(c & (DEPTH - 1)) * CHUNK_B;
        #pragma unroll
        for (int j = 0; j < 4; ++j) {
            const int row = j * 64 + crow;
            const int ok = (full || (row0 + row) < batch) ? 16 : 0;
            const float* src = x + (size_t)(row0 + row) * IN_F + c * 16 + cu * 4;
            cp_async16(dbase + (uint32_t)(row * 64 + cu * 16), src, ok);
        }
        cp_commit();
    };

    // A-fragment LDS geometry (verified R8/R9/R11 ordering)
    const uint32_t a0 = (uint32_t)((w * 16 + (lane >> 2)) * 64 + (lane & 3) * 8);

    float acc0[32], acc1[32];
    #pragma unroll
    for (int i = 0; i < 32; ++i) { acc0[i] = 0.f; acc1[i] = 0.f; }

    // ---- prologue: 3 chunks in flight ----
    issue(0); issue(1); issue(2);

    // ---- layer-1 mainloop over 48 chunks: ONE barrier per chunk ----
    #pragma unroll 1
    for (int c = 0; c < NSTEP1; ++c) {
        cp_wait<2>();                 // this thread's chunk-c copies landed
        __syncthreads();              // all threads' chunk-c data visible; all
                                      // warps provably done reading chunk c-1
        if (c + 3 < NSTEP1) issue(c + 3);   // writes slot (c-1)&3 — WAR-safe

        const uint32_t xb = sb + (uint32_t)(c & (DEPTH - 1)) * CHUNK_B;
        uint32_t af[8];
        {
            float2 v;
            asm volatile("ld.shared.v2.f32 {%0,%1}, [%2];" : "=f"(v.x), "=f"(v.y) : "r"(xb + a0));
            af[0] = pk2(v);
            asm volatile("ld.shared.v2.f32 {%0,%1}, [%2];" : "=f"(v.x), "=f"(v.y) : "r"(xb + a0 + 512));
            af[1] = pk2(v);
            asm volatile("ld.shared.v2.f32 {%0,%1}, [%2];" : "=f"(v.x), "=f"(v.y) : "r"(xb + a0 + 32));
            af[2] = pk2(v);
            asm volatile("ld.shared.v2.f32 {%0,%1}, [%2];" : "=f"(v.x), "=f"(v.y) : "r"(xb + a0 + 544));
            af[3] = pk2(v);
            asm volatile("ld.shared.v2.f32 {%0,%1}, [%2];" : "=f"(v.x), "=f"(v.y) : "r"(xb + a0 + 8192));
            af[4] = pk2(v);
            asm volatile("ld.shared.v2.f32 {%0,%1}, [%2];" : "=f"(v.x), "=f"(v.y) : "r"(xb + a0 + 8704));
            af[5] = pk2(v);
            asm volatile("ld.shared.v2.f32 {%0,%1}, [%2];" : "=f"(v.x), "=f"(v.y) : "r"(xb + a0 + 8224));
            af[6] = pk2(v);
            asm volatile("ld.shared.v2.f32 {%0,%1}, [%2];" : "=f"(v.x), "=f"(v.y) : "r"(xb + a0 + 8736));
            af[7] = pk2(v);
        }

        const uint2* wf = g_w1m + (size_t)c * 256 + lane;
        #pragma unroll
        for (int nb = 0; nb < 8; ++nb) {
            const uint2 f = __ldg(wf + nb * 32);
            mma16816(acc0 + nb * 4, af,     f.x, f.y);
            mma16816(acc1 + nb * 4, af + 4, f.x, f.y);
        }
    }

    // ---- h1 = relu(acc + b1), packed into A-fragment registers ----
    uint32_t hlo0[8], hhi0[8], hlo1[8], hhi1[8];
    #pragma unroll
    for (int nb = 0; nb < 8; ++nb) {
        const int n = nb * 8 + (lane & 3) * 2;
        const float ba = __ldg(b1 + n), bb = __ldg(b1 + n + 1);
        hlo0[nb] = pkh(__float2half_rn(fmaxf(acc0[nb * 4 + 0] + ba, 0.f)),
                       __float2half_rn(fmaxf(acc0[nb * 4 + 1] + bb, 0.f)));
        hhi0[nb] = pkh(__float2half_rn(fmaxf(acc0[nb * 4 + 2] + ba, 0.f)),
                       __float2half_rn(fmaxf(acc0[nb * 4 + 3] + bb, 0.f)));
        hlo1[nb] = pkh(__float2half_rn(fmaxf(acc1[nb * 4 + 0] + ba, 0.f)),
                       __float2half_rn(fmaxf(acc1[nb * 4 + 1] + bb, 0.f)));
        hhi1[nb] = pkh(__float2half_rn(fmaxf(acc1[nb * 4 + 2] + ba, 0.f)),
                       __float2half_rn(fmaxf(acc1[nb * 4 + 3] + bb, 0.f)));
    }

    // ---- layer-2 GEMM (K=64), A from registers, main + residual B ----
    float ac20[32], ac21[32];
    #pragma unroll
    for (int i = 0; i < 32; ++i) { ac20[i] = 0.f; ac21[i] = 0.f; }
    #pragma unroll
    for (int s = 0; s < NSTEP2; ++s) {
        const uint32_t a0r[4] = { hlo0[2 * s], hhi0[2 * s], hlo0[2 * s + 1], hhi0[2 * s + 1] };
        const uint32_t a1r[4] = { hlo1[2 * s], hhi1[2 * s], hlo1[2 * s + 1], hhi1[2 * s + 1] };
        const uint4* wf = g_w2f + (size_t)s * 256 + lane;
        #pragma unroll
        for (int nb = 0; nb < 8; ++nb) {
            const uint4 f = __ldg(wf + nb * 32);
            mma16816(ac20 + nb * 4, a0r, f.x, f.y);
            mma16816(ac20 + nb * 4, a0r, f.z, f.w);
            mma16816(ac21 + nb * 4, a1r, f.x, f.y);
            mma16816(ac21 + nb * 4, a1r, f.z, f.w);
        }
    }

    // ---- epilogue: out = relu(ac2 + b2) . w3 + b3 ----
    {
        const float b3v = __ldg(b3);
        #pragma unroll
        for (int st = 0; st < 2; ++st) {
            const float* ac = st ? ac21 : ac20;
            float pA = 0.f, pB = 0.f;
            #pragma unroll
            for (int nb = 0; nb < 8; ++nb) {
                const int n = nb * 8 + (lane & 3) * 2;
                const float ba = __ldg(b2 + n), bb = __ldg(b2 + n + 1);
                const float wa = g_w3[n],       wb = g_w3[n + 1];
                pA += fmaxf(ac[nb * 4 + 0] + ba, 0.f) * wa
                    + fmaxf(ac[nb * 4 + 1] + bb, 0.f) * wb;
                pB += fmaxf(ac[nb * 4 + 2] + ba, 0.f) * wa
                    + fmaxf(ac[nb * 4 + 3] + bb, 0.f) * wb;
            }
            pA += __shfl_xor_sync(0xffffffffu, pA, 1);
            pA += __shfl_xor_sync(0xffffffffu, pA, 2);
            pB += __shfl_xor_sync(0xffffffffu, pB, 1);
            pB += __shfl_xor_sync(0xffffffffu, pB, 2);
            if ((lane & 3) == 0) {
                const int rA = row0 + st * 128 + w * 16 + (lane >> 2);
                if (rA < batch)     out[rA]     = pA + b3v;
                if (rA + 8 < batch) out[rA + 8] = pB + b3v;
            }
        }
    }
}

// ---------------------------------------------------------------------------
extern "C" void kernel_launch(void* const* d_in, const int* in_sizes, int n_in,
                              void* d_out, int out_size)
{
    const float* x    = (const float*)d_in[0];
    const int*   idx1 = (const int*)  d_in[1];
    const float* val1 = (const float*)d_in[2];
    const float* b1   = (const float*)d_in[3];
    const int*   idx2 = (const int*)  d_in[4];
    const float* val2 = (const float*)d_in[5];
    const float* b2   = (const float*)d_in[6];
    const int*   idx3 = (const int*)  d_in[7];
    const float* val3 = (const float*)d_in[8];
    const float* b3   = (const float*)d_in[9];

    const int nnz1  = in_sizes[1] / 2;
    const int nnz2  = in_sizes[4] / 2;
    const int nnz3  = in_sizes[7] / 2;
    const int batch = in_sizes[0] / IN_F;

    const int smem_bytes = DEPTH * CHUNK_B;   // 65536
    cudaFuncSetAttribute(mma_kernel, cudaFuncAttributeMaxDynamicSharedMemorySize, smem_bytes);

    zero_kernel<<<64, 256>>>();
    scatter_kernel<<<32, 256>>>(idx1, val1, nnz1, idx2, val2, nnz2, idx3, val3, nnz3);
    pack_kernel<<<NSTEP1 + 1, THREADS>>>();

    const int blocks = (batch + MTILE - 1) / MTILE;
    mma_kernel<<<blocks, THREADS, smem_bytes>>>(x, b1, b2, b3, (float*)d_out, batch);
}